// round 1
// baseline (speedup 1.0000x reference)
#include <cuda_runtime.h>
#include <math.h>
#include <float.h>

#define NMAX 100000
#define EMAX 400000
#define ETOTMAX (EMAX + NMAX)
#define GMAX 4096
#define FMAX 256

// ---------------- scratch (static device globals; no allocation) ----------------
__device__ float g_bufA[NMAX * FMAX];   // h = x @ W
__device__ float g_bufB[NMAX * FMAX];   // ping
__device__ float g_bufC[NMAX * FMAX];   // pong
__device__ float g_esrc[NMAX * 4];
__device__ float g_edst[NMAX * 4];
__device__ float g_m[NMAX * 4];
__device__ float g_den[NMAX * 4];
__device__ float g_ebuf[ETOTMAX * 4];
__device__ float g_pool[GMAX * 128];
__device__ float g_cnt[GMAX];

// ---------------- helpers ----------------
__device__ __forceinline__ void atomicMaxFloat(float* addr, float v) {
    // valid for all IEEE floats given init = -FLT_MAX
    if (v >= 0.0f) atomicMax((int*)addr, __float_as_int(v));
    else           atomicMin((unsigned int*)addr, __float_as_uint(v));
}

// ---------------- GEMM: C[M,Ncol] = A[M,K] @ B[K,Ncol] ----------------
// BM=BN=64, BK=16, 256 threads, 4x4 per thread. K % 16 == 0, Ncol % 64 == 0.
__global__ void gemm_kernel(const float* __restrict__ A, const float* __restrict__ B,
                            float* __restrict__ C, int M, int K, int Ncol) {
    __shared__ float As[16][65];
    __shared__ float Bs[16][65];
    const int bm = blockIdx.y * 64;
    const int bn = blockIdx.x * 64;
    const int tid = threadIdx.x;
    const int tm = (tid / 16) * 4;
    const int tn = (tid % 16) * 4;
    float acc[4][4] = {};

    for (int k0 = 0; k0 < K; k0 += 16) {
        #pragma unroll
        for (int i = tid; i < 64 * 16; i += 256) {
            int m = i / 16, k = i % 16;
            As[k][m] = (bm + m < M) ? A[(size_t)(bm + m) * K + k0 + k] : 0.0f;
        }
        #pragma unroll
        for (int i = tid; i < 16 * 64; i += 256) {
            int k = i / 64, n = i % 64;
            Bs[k][n] = B[(size_t)(k0 + k) * Ncol + bn + n];
        }
        __syncthreads();
        #pragma unroll
        for (int k = 0; k < 16; k++) {
            float a[4], b[4];
            #pragma unroll
            for (int i = 0; i < 4; i++) a[i] = As[k][tm + i];
            #pragma unroll
            for (int j = 0; j < 4; j++) b[j] = Bs[k][tn + j];
            #pragma unroll
            for (int i = 0; i < 4; i++)
                #pragma unroll
                for (int j = 0; j < 4; j++) acc[i][j] += a[i] * b[j];
        }
        __syncthreads();
    }
    #pragma unroll
    for (int i = 0; i < 4; i++) {
        int m = bm + tm + i;
        if (m < M) {
            #pragma unroll
            for (int j = 0; j < 4; j++) C[(size_t)m * Ncol + bn + tn + j] = acc[i][j];
        }
    }
}

// ---------------- attention scores: e_src/e_dst = <h[n,h,:], a[h,:]> ----------------
// one warp per (n, head)
__global__ void scores_kernel(const float* __restrict__ h,
                              const float* __restrict__ a_s, const float* __restrict__ a_d,
                              float* __restrict__ esrc, float* __restrict__ edst,
                              int N, int H, int C) {
    int warp = (blockIdx.x * blockDim.x + threadIdx.x) >> 5;
    int lane = threadIdx.x & 31;
    if (warp >= N * H) return;
    int n = warp / H, hh = warp % H;
    const float* hp = h + (size_t)n * H * C + hh * C;
    float s = 0.0f, d = 0.0f;
    for (int c = lane; c < C; c += 32) {
        float v = hp[c];
        s += v * a_s[hh * C + c];
        d += v * a_d[hh * C + c];
    }
    #pragma unroll
    for (int o = 16; o; o >>= 1) {
        s += __shfl_down_sync(0xffffffffu, s, o);
        d += __shfl_down_sync(0xffffffffu, d, o);
    }
    if (lane == 0) { esrc[warp] = s; edst[warp] = d; }
}

__global__ void init_md_kernel(float* __restrict__ m, float* __restrict__ den, int n) {
    int t = blockIdx.x * blockDim.x + threadIdx.x;
    if (t < n) { m[t] = -FLT_MAX; den[t] = 0.0f; }
}

// ---------------- edge pass 1: leaky-relu score + segment max ----------------
__global__ void edge_max_kernel(const int* __restrict__ ei,
                                const float* __restrict__ esrc, const float* __restrict__ edst,
                                float* __restrict__ ebuf, float* __restrict__ m,
                                int E, int N, int H) {
    int t = blockIdx.x * blockDim.x + threadIdx.x;
    int Etot = E + N;
    if (t >= Etot * H) return;
    int e = t / H, hh = t % H;
    int s, d;
    if (e < E) { s = ei[e]; d = ei[E + e]; } else { s = d = e - E; }
    float v = esrc[s * H + hh] + edst[d * H + hh];
    v = (v > 0.0f) ? v : 0.2f * v;
    ebuf[t] = v;
    atomicMaxFloat(&m[d * H + hh], v);
}

// ---------------- edge pass 2: exp + segment sum ----------------
__global__ void edge_exp_kernel(const int* __restrict__ ei,
                                float* __restrict__ ebuf,
                                const float* __restrict__ m, float* __restrict__ den,
                                int E, int N, int H) {
    int t = blockIdx.x * blockDim.x + threadIdx.x;
    int Etot = E + N;
    if (t >= Etot * H) return;
    int e = t / H, hh = t % H;
    int d = (e < E) ? ei[E + e] : (e - E);
    float ex = expf(ebuf[t] - m[d * H + hh]);
    ebuf[t] = ex;
    atomicAdd(&den[d * H + hh], ex);
}

// ---------------- edge pass 3: weighted aggregation (atomic scatter) ----------------
// thread per (edge, 4-feature chunk)
__global__ void aggregate_kernel(const int* __restrict__ ei,
                                 const float* __restrict__ h,
                                 const float* __restrict__ ebuf, const float* __restrict__ den,
                                 float* __restrict__ out,
                                 int E, int N, int H, int C) {
    int F4 = (H * C) >> 2;
    int t = blockIdx.x * blockDim.x + threadIdx.x;
    int Etot = E + N;
    if (t >= Etot * F4) return;
    int e = t / F4, c4 = t % F4;
    int s, d;
    if (e < E) { s = ei[e]; d = ei[E + e]; } else { s = d = e - E; }
    int hh = (c4 * 4) / C;
    float alpha = ebuf[e * H + hh] / fmaxf(den[d * H + hh], 1e-16f);
    float4 hv = *(const float4*)(h + (size_t)s * H * C + c4 * 4);
    float* op = out + (size_t)d * H * C + c4 * 4;
    atomicAdd(op + 0, alpha * hv.x);
    atomicAdd(op + 1, alpha * hv.y);
    atomicAdd(op + 2, alpha * hv.z);
    atomicAdd(op + 3, alpha * hv.w);
}

// ---------------- bias (+ optional ELU) ----------------
__global__ void bias_act_kernel(float* __restrict__ out, const float* __restrict__ b,
                                int N, int F, int do_elu) {
    int t = blockIdx.x * blockDim.x + threadIdx.x;
    if (t >= N * F) return;
    float v = out[t] + b[t % F];
    if (do_elu) v = (v > 0.0f) ? v : expm1f(v);
    out[t] = v;
}

// ---------------- pooling ----------------
__global__ void pool_feat_kernel(const float* __restrict__ h, const int* __restrict__ batch,
                                 float* __restrict__ pool, int N, int F) {
    int t = blockIdx.x * blockDim.x + threadIdx.x;
    if (t >= N * F) return;
    int n = t / F, f = t % F;
    atomicAdd(&pool[batch[n] * F + f], h[(size_t)n * F + f]);
}

__global__ void pool_cnt_kernel(const int* __restrict__ batch, float* __restrict__ cnt, int N) {
    int t = blockIdx.x * blockDim.x + threadIdx.x;
    if (t < N) atomicAdd(&cnt[batch[t]], 1.0f);
}

// ---------------- MLP readout: 128 -> 64 -> 32 -> 4 ----------------
__global__ void mlp_kernel(const float* __restrict__ pool, const float* __restrict__ cnt,
                           const float* __restrict__ mW0, const float* __restrict__ mb0,
                           const float* __restrict__ mW1, const float* __restrict__ mb1,
                           const float* __restrict__ mW2, const float* __restrict__ mb2,
                           float* __restrict__ out, int G) {
    __shared__ float p[128], y1[64], y2[32];
    int g = blockIdx.x, t = threadIdx.x;
    if (g >= G) return;
    float c = fmaxf(cnt[g], 1.0f);
    p[t] = pool[(size_t)g * 128 + t] / c;
    __syncthreads();
    if (t < 64) {
        float s = mb0[t];
        #pragma unroll 8
        for (int i = 0; i < 128; i++) s += p[i] * mW0[i * 64 + t];
        y1[t] = fmaxf(s, 0.0f);
    }
    __syncthreads();
    if (t < 32) {
        float s = mb1[t];
        #pragma unroll 8
        for (int i = 0; i < 64; i++) s += y1[i] * mW1[i * 32 + t];
        y2[t] = fmaxf(s, 0.0f);
    }
    __syncthreads();
    if (t < 4) {
        float s = mb2[t];
        #pragma unroll
        for (int i = 0; i < 32; i++) s += y2[i] * mW2[i * 4 + t];
        out[g * 4 + t] = s;
    }
}

// ---------------- host orchestration ----------------
static void run_gat_layer(const float* x_in, int K, int H, int C,
                          const float* W, const float* a_s, const float* a_d, const float* b,
                          int do_elu,
                          const int* ei, int E, int N,
                          float* hbuf, float* outbuf,
                          float* esrc, float* edst, float* m, float* den, float* ebuf) {
    int F = H * C;
    int Etot = E + N;
    // h = x @ W
    dim3 ggrid(F / 64, (N + 63) / 64);
    gemm_kernel<<<ggrid, 256>>>(x_in, W, hbuf, N, K, F);
    // scores
    scores_kernel<<<(N * H * 32 + 255) / 256, 256>>>(hbuf, a_s, a_d, esrc, edst, N, H, C);
    // init m/den
    init_md_kernel<<<(N * H + 255) / 256, 256>>>(m, den, N * H);
    // edge passes
    edge_max_kernel<<<(Etot * H + 255) / 256, 256>>>(ei, esrc, edst, ebuf, m, E, N, H);
    edge_exp_kernel<<<(Etot * H + 255) / 256, 256>>>(ei, ebuf, m, den, E, N, H);
    // aggregate
    cudaMemsetAsync(outbuf, 0, (size_t)N * F * sizeof(float));
    int F4 = F / 4;
    aggregate_kernel<<<((long long)Etot * F4 + 255) / 256, 256>>>(ei, hbuf, ebuf, den, outbuf, E, N, H, C);
    // bias + activation
    bias_act_kernel<<<(N * F + 255) / 256, 256>>>(outbuf, b, N, F, do_elu);
}

extern "C" void kernel_launch(void* const* d_in, const int* in_sizes, int n_in,
                              void* d_out, int out_size) {
    const float* x     = (const float*)d_in[0];
    const int*   ei    = (const int*)d_in[1];
    const int*   batch = (const int*)d_in[2];
    const float* W0  = (const float*)d_in[4];
    const float* as0 = (const float*)d_in[5];
    const float* ad0 = (const float*)d_in[6];
    const float* b0  = (const float*)d_in[7];
    const float* W1  = (const float*)d_in[8];
    const float* as1 = (const float*)d_in[9];
    const float* ad1 = (const float*)d_in[10];
    const float* b1  = (const float*)d_in[11];
    const float* W2  = (const float*)d_in[12];
    const float* as2 = (const float*)d_in[13];
    const float* ad2 = (const float*)d_in[14];
    const float* b2  = (const float*)d_in[15];
    const float* W3  = (const float*)d_in[16];
    const float* as3 = (const float*)d_in[17];
    const float* ad3 = (const float*)d_in[18];
    const float* b3  = (const float*)d_in[19];
    const float* mW0 = (const float*)d_in[20];
    const float* mb0 = (const float*)d_in[21];
    const float* mW1 = (const float*)d_in[22];
    const float* mb1 = (const float*)d_in[23];
    const float* mW2 = (const float*)d_in[24];
    const float* mb2 = (const float*)d_in[25];

    int N = in_sizes[0] / 64;
    int E = in_sizes[1] / 2;
    int G = out_size / 4;

    float *bufA, *bufB, *bufC, *esrc, *edst, *m, *den, *ebuf, *pool, *cnt;
    cudaGetSymbolAddress((void**)&bufA, g_bufA);
    cudaGetSymbolAddress((void**)&bufB, g_bufB);
    cudaGetSymbolAddress((void**)&bufC, g_bufC);
    cudaGetSymbolAddress((void**)&esrc, g_esrc);
    cudaGetSymbolAddress((void**)&edst, g_edst);
    cudaGetSymbolAddress((void**)&m,    g_m);
    cudaGetSymbolAddress((void**)&den,  g_den);
    cudaGetSymbolAddress((void**)&ebuf, g_ebuf);
    cudaGetSymbolAddress((void**)&pool, g_pool);
    cudaGetSymbolAddress((void**)&cnt,  g_cnt);

    // layer 0: x[N,64] -> bufB[N,256]
    run_gat_layer(x,    64, 4,  64, W0, as0, ad0, b0, 1, ei, E, N, bufA, bufB, esrc, edst, m, den, ebuf);
    // layer 1: bufB -> bufC
    run_gat_layer(bufB, 256, 4, 64, W1, as1, ad1, b1, 1, ei, E, N, bufA, bufC, esrc, edst, m, den, ebuf);
    // layer 2: bufC -> bufB
    run_gat_layer(bufC, 256, 4, 64, W2, as2, ad2, b2, 1, ei, E, N, bufA, bufB, esrc, edst, m, den, ebuf);
    // layer 3: bufB -> bufC[N,128], no elu, H=1
    run_gat_layer(bufB, 256, 1, 128, W3, as3, ad3, b3, 0, ei, E, N, bufA, bufC, esrc, edst, m, den, ebuf);

    // global mean pool
    cudaMemsetAsync(pool, 0, (size_t)G * 128 * sizeof(float));
    cudaMemsetAsync(cnt,  0, (size_t)G * sizeof(float));
    pool_feat_kernel<<<(N * 128 + 255) / 256, 256>>>(bufC, batch, pool, N, 128);
    pool_cnt_kernel<<<(N + 255) / 256, 256>>>(batch, cnt, N);

    // MLP readout
    mlp_kernel<<<G, 128>>>(pool, cnt, mW0, mb0, mW1, mb1, mW2, mb2, (float*)d_out, G);
}

// round 2
// speedup vs baseline: 1.9104x; 1.9104x over previous
#include <cuda_runtime.h>
#include <math.h>
#include <float.h>

#define NMAX 100000
#define EMAX 400000
#define ETOTMAX (EMAX + NMAX)
#define GMAX 4096
#define FMAX 256

// ---------------- scratch (static device globals; no allocation) ----------------
__device__ float g_bufA[NMAX * FMAX];   // h = x @ W
__device__ float g_bufB[NMAX * FMAX];   // ping
__device__ float g_bufC[NMAX * FMAX];   // pong
__device__ float g_esrc[NMAX * 4];
__device__ float g_edst[NMAX * 4];
__device__ float g_pool[GMAX * 128];
__device__ float g_cnt[GMAX];
// CSR
__device__ int g_rowptr[NMAX + 1];
__device__ int g_fill[NMAX];        // also used as counts buffer
__device__ int g_col[ETOTMAX];
__device__ int g_blksum[512];

// ================= CSR build =================
__global__ void count_init_kernel(int* __restrict__ cnt, int N) {
    int t = blockIdx.x * blockDim.x + threadIdx.x;
    if (t < N) cnt[t] = 1;   // self loop
}
__global__ void count_edges_kernel(const int* __restrict__ ei, int* __restrict__ cnt, int E) {
    int t = blockIdx.x * blockDim.x + threadIdx.x;
    if (t < E) atomicAdd(&cnt[ei[E + t]], 1);
}
// exclusive scan, 1024 items per block (256 threads x 4)
__global__ void scan_block_kernel(const int* __restrict__ in, int* __restrict__ out,
                                  int* __restrict__ blksum, int n) {
    __shared__ int wsum[8];
    int t = threadIdx.x, blk = blockIdx.x;
    int base = blk * 1024 + t * 4;
    int v0 = (base + 0 < n) ? in[base + 0] : 0;
    int v1 = (base + 1 < n) ? in[base + 1] : 0;
    int v2 = (base + 2 < n) ? in[base + 2] : 0;
    int v3 = (base + 3 < n) ? in[base + 3] : 0;
    int tsum = v0 + v1 + v2 + v3;
    int lane = t & 31, w = t >> 5;
    int x = tsum;
    #pragma unroll
    for (int o = 1; o < 32; o <<= 1) {
        int y = __shfl_up_sync(0xffffffffu, x, o);
        if (lane >= o) x += y;
    }
    if (lane == 31) wsum[w] = x;
    __syncthreads();
    if (t < 8) {
        int y = wsum[t];
        #pragma unroll
        for (int o = 1; o < 8; o <<= 1) {
            int z = __shfl_up_sync(0xffu, y, o);
            if (t >= o) y += z;
        }
        wsum[t] = y;
    }
    __syncthreads();
    int woff = (w > 0) ? wsum[w - 1] : 0;
    int excl = woff + x - tsum;
    if (base + 0 < n) out[base + 0] = excl;
    if (base + 1 < n) out[base + 1] = excl + v0;
    if (base + 2 < n) out[base + 2] = excl + v0 + v1;
    if (base + 3 < n) out[base + 3] = excl + v0 + v1 + v2;
    if (t == 255) blksum[blk] = wsum[7];
}
__global__ void scan_sums_kernel(int* __restrict__ blksum, int nb) {
    int acc = 0;
    for (int i = 0; i < nb; i++) { int v = blksum[i]; blksum[i] = acc; acc += v; }
}
__global__ void add_off_kernel(int* __restrict__ out, const int* __restrict__ blksum, int n,
                               int tail_val) {
    int t = blockIdx.x * blockDim.x + threadIdx.x;
    if (t < n) out[t] += blksum[t >> 10];
    if (t == 0) out[n] = tail_val;
}
__global__ void copy_fill_kernel(const int* __restrict__ rowptr, int* __restrict__ fill, int N) {
    int t = blockIdx.x * blockDim.x + threadIdx.x;
    if (t < N) fill[t] = rowptr[t];
}
__global__ void fill_kernel(const int* __restrict__ ei, int* __restrict__ fill,
                            int* __restrict__ col, int E, int N) {
    int t = blockIdx.x * blockDim.x + threadIdx.x;
    int Etot = E + N;
    if (t >= Etot) return;
    int s, d;
    if (t < E) { s = ei[t]; d = ei[E + t]; } else { s = d = t - E; }
    int pos = atomicAdd(&fill[d], 1);
    col[pos] = s;
}

// ================= GEMM: C[M,Ncol] = A[M,K] @ B[K,Ncol] =================
// BM=BN=128, BK=8, 256 threads, 8x8 per thread, register prefetch.
// Requires K % 8 == 0, Ncol % 128 == 0, K % 4 == 0 for float4.
__global__ void gemm128_kernel(const float* __restrict__ A, const float* __restrict__ B,
                               float* __restrict__ C, int M, int K, int Ncol) {
    __shared__ float As[8][132];
    __shared__ float Bs[8][132];
    const int tid = threadIdx.x;
    const int bm = blockIdx.y * 128;
    const int bn = blockIdx.x * 128;

    const int am = tid >> 1;          // 0..127
    const int ak = (tid & 1) * 4;     // 0 or 4
    const int bk = tid >> 5;          // 0..7
    const int bn4 = (tid & 31) * 4;   // 0..124
    const bool arow_ok = (bm + am) < M;
    const float* Aptr = A + (size_t)(bm + am) * K + ak;
    const float* Bptr = B + (size_t)bk * Ncol + bn + bn4;

    const int ty = tid >> 4;          // 0..15
    const int tx = tid & 15;          // 0..15

    float acc[8][8] = {};
    float4 a4 = arow_ok ? *(const float4*)Aptr : make_float4(0.f, 0.f, 0.f, 0.f);
    float4 b4 = *(const float4*)Bptr;

    for (int k0 = 0; k0 < K; k0 += 8) {
        As[ak + 0][am] = a4.x; As[ak + 1][am] = a4.y;
        As[ak + 2][am] = a4.z; As[ak + 3][am] = a4.w;
        *(float4*)&Bs[bk][bn4] = b4;
        __syncthreads();
        if (k0 + 8 < K) {
            a4 = arow_ok ? *(const float4*)(Aptr + k0 + 8) : make_float4(0.f, 0.f, 0.f, 0.f);
            b4 = *(const float4*)(Bptr + (size_t)(k0 + 8) * Ncol);
        }
        #pragma unroll
        for (int kk = 0; kk < 8; kk++) {
            float4 A0 = *(const float4*)&As[kk][ty * 8];
            float4 A1 = *(const float4*)&As[kk][ty * 8 + 4];
            float4 B0 = *(const float4*)&Bs[kk][tx * 8];
            float4 B1 = *(const float4*)&Bs[kk][tx * 8 + 4];
            float a[8] = {A0.x, A0.y, A0.z, A0.w, A1.x, A1.y, A1.z, A1.w};
            float b[8] = {B0.x, B0.y, B0.z, B0.w, B1.x, B1.y, B1.z, B1.w};
            #pragma unroll
            for (int i = 0; i < 8; i++)
                #pragma unroll
                for (int j = 0; j < 8; j++) acc[i][j] = fmaf(a[i], b[j], acc[i][j]);
        }
        __syncthreads();
    }
    #pragma unroll
    for (int i = 0; i < 8; i++) {
        int m = bm + ty * 8 + i;
        if (m < M) {
            float* Cp = C + (size_t)m * Ncol + bn + tx * 8;
            *(float4*)Cp       = make_float4(acc[i][0], acc[i][1], acc[i][2], acc[i][3]);
            *(float4*)(Cp + 4) = make_float4(acc[i][4], acc[i][5], acc[i][6], acc[i][7]);
        }
    }
}

// ================= attention scores =================
__global__ void scores_kernel(const float* __restrict__ h,
                              const float* __restrict__ a_s, const float* __restrict__ a_d,
                              float* __restrict__ esrc, float* __restrict__ edst,
                              int N, int H, int C) {
    int warp = (blockIdx.x * blockDim.x + threadIdx.x) >> 5;
    int lane = threadIdx.x & 31;
    if (warp >= N * H) return;
    int n = warp / H, hh = warp % H;
    const float* hp = h + (size_t)n * H * C + hh * C;
    float s = 0.0f, d = 0.0f;
    for (int c = lane; c < C; c += 32) {
        float v = hp[c];
        s += v * a_s[hh * C + c];
        d += v * a_d[hh * C + c];
    }
    #pragma unroll
    for (int o = 16; o; o >>= 1) {
        s += __shfl_down_sync(0xffffffffu, s, o);
        d += __shfl_down_sync(0xffffffffu, d, o);
    }
    if (lane == 0) { esrc[warp] = s; edst[warp] = d; }
}

// ================= fused gather: softmax + aggregate + bias + ELU =================
// one warp per destination node
template<int H, int C>
__global__ void gat_gather_kernel(const float* __restrict__ h,
                                  const float* __restrict__ es, const float* __restrict__ ed,
                                  const int* __restrict__ rowptr, const int* __restrict__ col,
                                  const float* __restrict__ bias, float* __restrict__ out,
                                  int N, int do_elu) {
    constexpr int F = H * C;
    constexpr int CAP = 64;
    constexpr int NW = 8;
    __shared__ float shex[NW][CAP * H];
    __shared__ int   shsrc[NW][CAP];
    const int w = threadIdx.x >> 5, lane = threadIdx.x & 31;
    const int d = blockIdx.x * NW + w;
    if (d >= N) return;
    const int start = rowptr[d];
    const int deg = rowptr[d + 1] - start;

    float edv[H], mx[H];
    #pragma unroll
    for (int hh = 0; hh < H; hh++) { edv[hh] = ed[d * H + hh]; mx[hh] = -FLT_MAX; }

    // pass 1: scores + max
    for (int i0 = 0; i0 < deg; i0 += 32) {
        int i = i0 + lane;
        if (i < deg) {
            int s = col[start + i];
            if (i < CAP) shsrc[w][i] = s;
            #pragma unroll
            for (int hh = 0; hh < H; hh++) {
                float v = es[s * H + hh] + edv[hh];
                v = (v > 0.f) ? v : 0.2f * v;
                if (i < CAP) shex[w][i * H + hh] = v;
                mx[hh] = fmaxf(mx[hh], v);
            }
        }
    }
    #pragma unroll
    for (int hh = 0; hh < H; hh++)
        #pragma unroll
        for (int o = 16; o; o >>= 1) mx[hh] = fmaxf(mx[hh], __shfl_xor_sync(0xffffffffu, mx[hh], o));
    __syncwarp();

    // pass 2: exp + denom
    float den[H];
    #pragma unroll
    for (int hh = 0; hh < H; hh++) den[hh] = 0.f;
    for (int i0 = 0; i0 < deg; i0 += 32) {
        int i = i0 + lane;
        if (i < deg) {
            int s = (i < CAP) ? shsrc[w][i] : col[start + i];
            #pragma unroll
            for (int hh = 0; hh < H; hh++) {
                float v;
                if (i < CAP) v = shex[w][i * H + hh];
                else { v = es[s * H + hh] + edv[hh]; v = (v > 0.f) ? v : 0.2f * v; }
                float ex = expf(v - mx[hh]);
                if (i < CAP) shex[w][i * H + hh] = ex;
                den[hh] += ex;
            }
        }
    }
    float inv[H];
    #pragma unroll
    for (int hh = 0; hh < H; hh++) {
        #pragma unroll
        for (int o = 16; o; o >>= 1) den[hh] += __shfl_xor_sync(0xffffffffu, den[hh], o);
        inv[hh] = 1.f / fmaxf(den[hh], 1e-16f);
    }
    __syncwarp();

    // pass 3: weighted feature accumulation (coalesced rows)
    constexpr int NF = F / 32;
    float acc[NF] = {};
    for (int i = 0; i < deg; i++) {
        int s;
        float al[H];
        if (i < CAP) {
            s = shsrc[w][i];
            #pragma unroll
            for (int hh = 0; hh < H; hh++) al[hh] = shex[w][i * H + hh] * inv[hh];
        } else {
            s = col[start + i];
            #pragma unroll
            for (int hh = 0; hh < H; hh++) {
                float v = es[s * H + hh] + edv[hh];
                v = (v > 0.f) ? v : 0.2f * v;
                al[hh] = expf(v - mx[hh]) * inv[hh];
            }
        }
        const float* hr = h + (size_t)s * F;
        #pragma unroll
        for (int fc = 0; fc < NF; fc++) {
            constexpr int dummy = 0; (void)dummy;
            int hh = (fc * 32) / C;   // uniform since C % 32 == 0, C >= 64
            acc[fc] = fmaf(al[hh], hr[fc * 32 + lane], acc[fc]);
        }
    }
    #pragma unroll
    for (int fc = 0; fc < NF; fc++) {
        int f = fc * 32 + lane;
        float v = acc[fc] + bias[f];
        if (do_elu) v = (v > 0.f) ? v : expm1f(v);
        out[(size_t)d * F + f] = v;
    }
}

// ================= pooling =================
__global__ void pool_feat_kernel(const float* __restrict__ h, const int* __restrict__ batch,
                                 float* __restrict__ pool, int N, int F) {
    int t = blockIdx.x * blockDim.x + threadIdx.x;
    if (t >= N * F) return;
    int n = t / F, f = t % F;
    atomicAdd(&pool[batch[n] * F + f], h[(size_t)n * F + f]);
}
__global__ void pool_cnt_kernel(const int* __restrict__ batch, float* __restrict__ cnt, int N) {
    int t = blockIdx.x * blockDim.x + threadIdx.x;
    if (t < N) atomicAdd(&cnt[batch[t]], 1.0f);
}
__global__ void zero_pool_kernel(float* __restrict__ pool, float* __restrict__ cnt, int G) {
    int t = blockIdx.x * blockDim.x + threadIdx.x;
    if (t < G * 128) pool[t] = 0.f;
    if (t < G) cnt[t] = 0.f;
}

// ================= MLP readout: 128 -> 64 -> 32 -> 4 =================
__global__ void mlp_kernel(const float* __restrict__ pool, const float* __restrict__ cnt,
                           const float* __restrict__ mW0, const float* __restrict__ mb0,
                           const float* __restrict__ mW1, const float* __restrict__ mb1,
                           const float* __restrict__ mW2, const float* __restrict__ mb2,
                           float* __restrict__ out, int G) {
    __shared__ float p[128], y1[64], y2[32];
    int g = blockIdx.x, t = threadIdx.x;
    if (g >= G) return;
    float c = fmaxf(cnt[g], 1.0f);
    p[t] = pool[(size_t)g * 128 + t] / c;
    __syncthreads();
    if (t < 64) {
        float s = mb0[t];
        #pragma unroll 8
        for (int i = 0; i < 128; i++) s += p[i] * mW0[i * 64 + t];
        y1[t] = fmaxf(s, 0.0f);
    }
    __syncthreads();
    if (t < 32) {
        float s = mb1[t];
        #pragma unroll 8
        for (int i = 0; i < 64; i++) s += y1[i] * mW1[i * 32 + t];
        y2[t] = fmaxf(s, 0.0f);
    }
    __syncthreads();
    if (t < 4) {
        float s = mb2[t];
        #pragma unroll
        for (int i = 0; i < 32; i++) s += y2[i] * mW2[i * 4 + t];
        out[g * 4 + t] = s;
    }
}

// ================= host orchestration =================
extern "C" void kernel_launch(void* const* d_in, const int* in_sizes, int n_in,
                              void* d_out, int out_size) {
    const float* x     = (const float*)d_in[0];
    const int*   ei    = (const int*)d_in[1];
    const int*   batch = (const int*)d_in[2];
    const float* W0  = (const float*)d_in[4];
    const float* as0 = (const float*)d_in[5];
    const float* ad0 = (const float*)d_in[6];
    const float* b0  = (const float*)d_in[7];
    const float* W1  = (const float*)d_in[8];
    const float* as1 = (const float*)d_in[9];
    const float* ad1 = (const float*)d_in[10];
    const float* b1  = (const float*)d_in[11];
    const float* W2  = (const float*)d_in[12];
    const float* as2 = (const float*)d_in[13];
    const float* ad2 = (const float*)d_in[14];
    const float* b2  = (const float*)d_in[15];
    const float* W3  = (const float*)d_in[16];
    const float* as3 = (const float*)d_in[17];
    const float* ad3 = (const float*)d_in[18];
    const float* b3  = (const float*)d_in[19];
    const float* mW0 = (const float*)d_in[20];
    const float* mb0 = (const float*)d_in[21];
    const float* mW1 = (const float*)d_in[22];
    const float* mb1 = (const float*)d_in[23];
    const float* mW2 = (const float*)d_in[24];
    const float* mb2 = (const float*)d_in[25];

    int N = in_sizes[0] / 64;
    int E = in_sizes[1] / 2;
    int G = out_size / 4;
    int Etot = E + N;

    float *bufA, *bufB, *bufC, *esrc, *edst, *pool, *cnt;
    int *rowptr, *fill, *col, *blksum;
    cudaGetSymbolAddress((void**)&bufA, g_bufA);
    cudaGetSymbolAddress((void**)&bufB, g_bufB);
    cudaGetSymbolAddress((void**)&bufC, g_bufC);
    cudaGetSymbolAddress((void**)&esrc, g_esrc);
    cudaGetSymbolAddress((void**)&edst, g_edst);
    cudaGetSymbolAddress((void**)&pool, g_pool);
    cudaGetSymbolAddress((void**)&cnt,  g_cnt);
    cudaGetSymbolAddress((void**)&rowptr, g_rowptr);
    cudaGetSymbolAddress((void**)&fill,   g_fill);
    cudaGetSymbolAddress((void**)&col,    g_col);
    cudaGetSymbolAddress((void**)&blksum, g_blksum);

    // ---- build CSR (dst-grouped, self loops included) ----
    count_init_kernel<<<(N + 255) / 256, 256>>>(fill, N);
    count_edges_kernel<<<(E + 255) / 256, 256>>>(ei, fill, E);
    int nb = (N + 1023) / 1024;
    scan_block_kernel<<<nb, 256>>>(fill, rowptr, blksum, N);
    scan_sums_kernel<<<1, 1>>>(blksum, nb);
    add_off_kernel<<<(N + 255) / 256, 256>>>(rowptr, blksum, N, Etot);
    copy_fill_kernel<<<(N + 255) / 256, 256>>>(rowptr, fill, N);
    fill_kernel<<<(Etot + 255) / 256, 256>>>(ei, fill, col, E, N);

    // ---- 4 GAT layers ----
    // layer 0: x[N,64] -> bufB[N,256]
    gemm128_kernel<<<dim3(256 / 128, (N + 127) / 128), 256>>>(x, W0, bufA, N, 64, 256);
    scores_kernel<<<(N * 4 * 32 + 255) / 256, 256>>>(bufA, as0, ad0, esrc, edst, N, 4, 64);
    gat_gather_kernel<4, 64><<<(N + 7) / 8, 256>>>(bufA, esrc, edst, rowptr, col, b0, bufB, N, 1);
    // layer 1: bufB -> bufC
    gemm128_kernel<<<dim3(2, (N + 127) / 128), 256>>>(bufB, W1, bufA, N, 256, 256);
    scores_kernel<<<(N * 4 * 32 + 255) / 256, 256>>>(bufA, as1, ad1, esrc, edst, N, 4, 64);
    gat_gather_kernel<4, 64><<<(N + 7) / 8, 256>>>(bufA, esrc, edst, rowptr, col, b1, bufC, N, 1);
    // layer 2: bufC -> bufB
    gemm128_kernel<<<dim3(2, (N + 127) / 128), 256>>>(bufC, W2, bufA, N, 256, 256);
    scores_kernel<<<(N * 4 * 32 + 255) / 256, 256>>>(bufA, as2, ad2, esrc, edst, N, 4, 64);
    gat_gather_kernel<4, 64><<<(N + 7) / 8, 256>>>(bufA, esrc, edst, rowptr, col, b2, bufB, N, 1);
    // layer 3: bufB -> bufC[N,128], H=1, C=128, no ELU
    gemm128_kernel<<<dim3(1, (N + 127) / 128), 256>>>(bufB, W3, bufA, N, 256, 128);
    scores_kernel<<<(N * 1 * 32 + 255) / 256, 256>>>(bufA, as3, ad3, esrc, edst, N, 1, 128);
    gat_gather_kernel<1, 128><<<(N + 7) / 8, 256>>>(bufA, esrc, edst, rowptr, col, b3, bufC, N, 0);

    // ---- global mean pool ----
    zero_pool_kernel<<<(G * 128 + 255) / 256, 256>>>(pool, cnt, G);
    pool_feat_kernel<<<(N * 128 + 255) / 256, 256>>>(bufC, batch, pool, N, 128);
    pool_cnt_kernel<<<(N + 255) / 256, 256>>>(batch, cnt, N);

    // ---- MLP readout ----
    mlp_kernel<<<G, 128>>>(pool, cnt, mW0, mb0, mW1, mb1, mW2, mb2, (float*)d_out, G);
}

// round 3
// speedup vs baseline: 3.1937x; 1.6718x over previous
#include <cuda_runtime.h>
#include <math.h>
#include <float.h>

#define NMAX 100000
#define EMAX 400000
#define ETOTMAX (EMAX + NMAX)
#define GMAX 4096
#define FMAX 256

// ---------------- scratch (static device globals; no allocation) ----------------
__device__ float g_bufA[NMAX * FMAX];
__device__ float g_bufB[NMAX * FMAX];
__device__ float g_bufC[NMAX * FMAX];
__device__ float g_esrc[NMAX * 4];
__device__ float g_edst[NMAX * 4];
__device__ float g_pool[GMAX * 128];
__device__ float g_cnt[GMAX];
__device__ int g_rowptr[NMAX + 1];
__device__ int g_fill[NMAX];
__device__ int g_col[ETOTMAX];
__device__ int g_blksum[512];

// ================= CSR build =================
__global__ void count_init_kernel(int* __restrict__ cnt, int N) {
    int t = blockIdx.x * blockDim.x + threadIdx.x;
    if (t < N) cnt[t] = 1;
}
__global__ void count_edges_kernel(const int* __restrict__ ei, int* __restrict__ cnt, int E) {
    int t = blockIdx.x * blockDim.x + threadIdx.x;
    if (t < E) atomicAdd(&cnt[ei[E + t]], 1);
}
__global__ void scan_block_kernel(const int* __restrict__ in, int* __restrict__ out,
                                  int* __restrict__ blksum, int n) {
    __shared__ int wsum[8];
    int t = threadIdx.x, blk = blockIdx.x;
    int base = blk * 1024 + t * 4;
    int v0 = (base + 0 < n) ? in[base + 0] : 0;
    int v1 = (base + 1 < n) ? in[base + 1] : 0;
    int v2 = (base + 2 < n) ? in[base + 2] : 0;
    int v3 = (base + 3 < n) ? in[base + 3] : 0;
    int tsum = v0 + v1 + v2 + v3;
    int lane = t & 31, w = t >> 5;
    int x = tsum;
    #pragma unroll
    for (int o = 1; o < 32; o <<= 1) {
        int y = __shfl_up_sync(0xffffffffu, x, o);
        if (lane >= o) x += y;
    }
    if (lane == 31) wsum[w] = x;
    __syncthreads();
    if (t < 8) {
        int y = wsum[t];
        #pragma unroll
        for (int o = 1; o < 8; o <<= 1) {
            int z = __shfl_up_sync(0xffu, y, o);
            if (t >= o) y += z;
        }
        wsum[t] = y;
    }
    __syncthreads();
    int woff = (w > 0) ? wsum[w - 1] : 0;
    int excl = woff + x - tsum;
    if (base + 0 < n) out[base + 0] = excl;
    if (base + 1 < n) out[base + 1] = excl + v0;
    if (base + 2 < n) out[base + 2] = excl + v0 + v1;
    if (base + 3 < n) out[base + 3] = excl + v0 + v1 + v2;
    if (t == 255) blksum[blk] = wsum[7];
}
__global__ void scan_sums_kernel(int* __restrict__ blksum, int nb) {
    // single block, 256 threads: serial-free small scan
    __shared__ int sh[512];
    int t = threadIdx.x;
    int v = (t < nb) ? blksum[t] : 0;
    sh[t] = v;
    __syncthreads();
    // Hillis-Steele inclusive
    for (int o = 1; o < 256; o <<= 1) {
        int y = (t >= o) ? sh[t - o] : 0;
        __syncthreads();
        sh[t] += y;
        __syncthreads();
    }
    if (t < nb) blksum[t] = sh[t] - v;  // exclusive
}
__global__ void add_off_kernel(int* __restrict__ out, const int* __restrict__ blksum, int n,
                               int tail_val) {
    int t = blockIdx.x * blockDim.x + threadIdx.x;
    if (t < n) out[t] += blksum[t >> 10];
    if (t == 0) out[n] = tail_val;
}
__global__ void copy_fill_kernel(const int* __restrict__ rowptr, int* __restrict__ fill, int N) {
    int t = blockIdx.x * blockDim.x + threadIdx.x;
    if (t < N) fill[t] = rowptr[t];
}
__global__ void fill_kernel(const int* __restrict__ ei, int* __restrict__ fill,
                            int* __restrict__ col, int E, int N) {
    int t = blockIdx.x * blockDim.x + threadIdx.x;
    int Etot = E + N;
    if (t >= Etot) return;
    int s, d;
    if (t < E) { s = ei[t]; d = ei[E + t]; } else { s = d = t - E; }
    int pos = atomicAdd(&fill[d], 1);
    col[pos] = s;
}

// ================= TF32 tensor-core GEMM =================
// C[M,Ncol] = A[M,K] @ B[K,Ncol], row-major. BM=128, BN=128, BK=16.
// 256 threads = 8 warps (4 along M x 2 along N), warp tile 32x64.
// mma.sync.aligned.m16n8k8 tf32. Requires K%16==0, Ncol%128==0.
#define AS_STRIDE 20
#define BS_STRIDE 136
__global__ void __launch_bounds__(256, 2)
gemm_tf32_kernel(const float* __restrict__ A, const float* __restrict__ B,
                 float* __restrict__ C, int M, int K, int Ncol) {
    __shared__ unsigned As[128 * AS_STRIDE];   // [m][k], stride 20
    __shared__ unsigned Bs[16 * BS_STRIDE];    // [k][n], stride 136

    const int tid = threadIdx.x;
    const int bm = blockIdx.y * 128;
    const int bn = blockIdx.x * 128;
    const int warp = tid >> 5, lane = tid & 31;
    const int g = lane >> 2, tg = lane & 3;
    const int warp_m = (warp & 3) * 32;
    const int warp_n = (warp >> 2) * 64;

    // gmem load mapping: 512 float4 per tile, 2 per thread
    // A tile: float4 i -> row = i>>2, kq = i&3
    // B tile: float4 i -> k = i>>5,  n4 = (i&31)*4
    float4 pa[2], pb[2];
    #pragma unroll
    for (int u = 0; u < 2; u++) {
        int ia = tid + u * 256;
        int am = ia >> 2, akq = ia & 3;
        pa[u] = (bm + am < M) ? *(const float4*)(A + (size_t)(bm + am) * K + akq * 4)
                              : make_float4(0.f, 0.f, 0.f, 0.f);
        int ib = tid + u * 256;
        int bk = ib >> 5, bn4 = (ib & 31) * 4;
        pb[u] = *(const float4*)(B + (size_t)bk * Ncol + bn + bn4);
    }

    float acc[2][8][4];
    #pragma unroll
    for (int mt = 0; mt < 2; mt++)
        #pragma unroll
        for (int nt = 0; nt < 8; nt++)
            #pragma unroll
            for (int r = 0; r < 4; r++) acc[mt][nt][r] = 0.f;

    for (int k0 = 0; k0 < K; k0 += 16) {
        // store prefetched tile to smem with fp32->tf32 rounding
        #pragma unroll
        for (int u = 0; u < 2; u++) {
            int ia = tid + u * 256;
            int am = ia >> 2, akq = (ia & 3) * 4;
            unsigned t0, t1, t2, t3;
            asm("cvt.rna.tf32.f32 %0, %1;" : "=r"(t0) : "f"(pa[u].x));
            asm("cvt.rna.tf32.f32 %0, %1;" : "=r"(t1) : "f"(pa[u].y));
            asm("cvt.rna.tf32.f32 %0, %1;" : "=r"(t2) : "f"(pa[u].z));
            asm("cvt.rna.tf32.f32 %0, %1;" : "=r"(t3) : "f"(pa[u].w));
            As[am * AS_STRIDE + akq + 0] = t0;
            As[am * AS_STRIDE + akq + 1] = t1;
            As[am * AS_STRIDE + akq + 2] = t2;
            As[am * AS_STRIDE + akq + 3] = t3;
            int ib = tid + u * 256;
            int bk = ib >> 5, bn4 = (ib & 31) * 4;
            asm("cvt.rna.tf32.f32 %0, %1;" : "=r"(t0) : "f"(pb[u].x));
            asm("cvt.rna.tf32.f32 %0, %1;" : "=r"(t1) : "f"(pb[u].y));
            asm("cvt.rna.tf32.f32 %0, %1;" : "=r"(t2) : "f"(pb[u].z));
            asm("cvt.rna.tf32.f32 %0, %1;" : "=r"(t3) : "f"(pb[u].w));
            Bs[bk * BS_STRIDE + bn4 + 0] = t0;
            Bs[bk * BS_STRIDE + bn4 + 1] = t1;
            Bs[bk * BS_STRIDE + bn4 + 2] = t2;
            Bs[bk * BS_STRIDE + bn4 + 3] = t3;
        }
        __syncthreads();

        if (k0 + 16 < K) {
            #pragma unroll
            for (int u = 0; u < 2; u++) {
                int ia = tid + u * 256;
                int am = ia >> 2, akq = ia & 3;
                pa[u] = (bm + am < M)
                    ? *(const float4*)(A + (size_t)(bm + am) * K + k0 + 16 + akq * 4)
                    : make_float4(0.f, 0.f, 0.f, 0.f);
                int ib = tid + u * 256;
                int bk = ib >> 5, bn4 = (ib & 31) * 4;
                pb[u] = *(const float4*)(B + (size_t)(k0 + 16 + bk) * Ncol + bn + bn4);
            }
        }

        #pragma unroll
        for (int kk = 0; kk < 2; kk++) {
            unsigned afr[2][4], bfr[8][2];
            #pragma unroll
            for (int mt = 0; mt < 2; mt++) {
                int r0 = warp_m + mt * 16 + g;
                afr[mt][0] = As[r0 * AS_STRIDE + kk * 8 + tg];
                afr[mt][1] = As[(r0 + 8) * AS_STRIDE + kk * 8 + tg];
                afr[mt][2] = As[r0 * AS_STRIDE + kk * 8 + tg + 4];
                afr[mt][3] = As[(r0 + 8) * AS_STRIDE + kk * 8 + tg + 4];
            }
            #pragma unroll
            for (int nt = 0; nt < 8; nt++) {
                int c = warp_n + nt * 8 + g;
                bfr[nt][0] = Bs[(kk * 8 + tg) * BS_STRIDE + c];
                bfr[nt][1] = Bs[(kk * 8 + tg + 4) * BS_STRIDE + c];
            }
            #pragma unroll
            for (int mt = 0; mt < 2; mt++)
                #pragma unroll
                for (int nt = 0; nt < 8; nt++) {
                    asm volatile(
                        "mma.sync.aligned.m16n8k8.row.col.f32.tf32.tf32.f32 "
                        "{%0,%1,%2,%3}, {%4,%5,%6,%7}, {%8,%9}, {%0,%1,%2,%3};"
                        : "+f"(acc[mt][nt][0]), "+f"(acc[mt][nt][1]),
                          "+f"(acc[mt][nt][2]), "+f"(acc[mt][nt][3])
                        : "r"(afr[mt][0]), "r"(afr[mt][1]), "r"(afr[mt][2]), "r"(afr[mt][3]),
                          "r"(bfr[nt][0]), "r"(bfr[nt][1]));
                }
        }
        __syncthreads();
    }

    // epilogue
    #pragma unroll
    for (int mt = 0; mt < 2; mt++) {
        int r0 = bm + warp_m + mt * 16 + g;
        int r1 = r0 + 8;
        #pragma unroll
        for (int nt = 0; nt < 8; nt++) {
            int c = bn + warp_n + nt * 8 + 2 * tg;
            if (r0 < M) *(float2*)(C + (size_t)r0 * Ncol + c) = make_float2(acc[mt][nt][0], acc[mt][nt][1]);
            if (r1 < M) *(float2*)(C + (size_t)r1 * Ncol + c) = make_float2(acc[mt][nt][2], acc[mt][nt][3]);
        }
    }
}

// ================= attention scores =================
__global__ void scores_kernel(const float* __restrict__ h,
                              const float* __restrict__ a_s, const float* __restrict__ a_d,
                              float* __restrict__ esrc, float* __restrict__ edst,
                              int N, int H, int C) {
    int warp = (blockIdx.x * blockDim.x + threadIdx.x) >> 5;
    int lane = threadIdx.x & 31;
    if (warp >= N * H) return;
    int n = warp / H, hh = warp % H;
    const float* hp = h + (size_t)n * H * C + hh * C;
    float s = 0.0f, d = 0.0f;
    for (int c = lane; c < C; c += 32) {
        float v = hp[c];
        s += v * a_s[hh * C + c];
        d += v * a_d[hh * C + c];
    }
    #pragma unroll
    for (int o = 16; o; o >>= 1) {
        s += __shfl_down_sync(0xffffffffu, s, o);
        d += __shfl_down_sync(0xffffffffu, d, o);
    }
    if (lane == 0) { esrc[warp] = s; edst[warp] = d; }
}

// ================= fused gather: softmax + aggregate + bias + ELU =================
template<int H, int C>
__global__ void gat_gather_kernel(const float* __restrict__ h,
                                  const float* __restrict__ es, const float* __restrict__ ed,
                                  const int* __restrict__ rowptr, const int* __restrict__ col,
                                  const float* __restrict__ bias, float* __restrict__ out,
                                  int N, int do_elu) {
    constexpr int F = H * C;
    constexpr int CAP = 64;
    constexpr int NW = 8;
    __shared__ float shex[NW][CAP * H];
    __shared__ int   shsrc[NW][CAP];
    const int w = threadIdx.x >> 5, lane = threadIdx.x & 31;
    const int d = blockIdx.x * NW + w;
    if (d >= N) return;
    const int start = rowptr[d];
    const int deg = rowptr[d + 1] - start;

    float edv[H], mx[H];
    #pragma unroll
    for (int hh = 0; hh < H; hh++) { edv[hh] = ed[d * H + hh]; mx[hh] = -FLT_MAX; }

    for (int i0 = 0; i0 < deg; i0 += 32) {
        int i = i0 + lane;
        if (i < deg) {
            int s = col[start + i];
            if (i < CAP) shsrc[w][i] = s;
            #pragma unroll
            for (int hh = 0; hh < H; hh++) {
                float v = es[s * H + hh] + edv[hh];
                v = (v > 0.f) ? v : 0.2f * v;
                if (i < CAP) shex[w][i * H + hh] = v;
                mx[hh] = fmaxf(mx[hh], v);
            }
        }
    }
    #pragma unroll
    for (int hh = 0; hh < H; hh++)
        #pragma unroll
        for (int o = 16; o; o >>= 1) mx[hh] = fmaxf(mx[hh], __shfl_xor_sync(0xffffffffu, mx[hh], o));
    __syncwarp();

    float den[H];
    #pragma unroll
    for (int hh = 0; hh < H; hh++) den[hh] = 0.f;
    for (int i0 = 0; i0 < deg; i0 += 32) {
        int i = i0 + lane;
        if (i < deg) {
            int s = (i < CAP) ? shsrc[w][i] : col[start + i];
            #pragma unroll
            for (int hh = 0; hh < H; hh++) {
                float v;
                if (i < CAP) v = shex[w][i * H + hh];
                else { v = es[s * H + hh] + edv[hh]; v = (v > 0.f) ? v : 0.2f * v; }
                float ex = expf(v - mx[hh]);
                if (i < CAP) shex[w][i * H + hh] = ex;
                den[hh] += ex;
            }
        }
    }
    float inv[H];
    #pragma unroll
    for (int hh = 0; hh < H; hh++) {
        #pragma unroll
        for (int o = 16; o; o >>= 1) den[hh] += __shfl_xor_sync(0xffffffffu, den[hh], o);
        inv[hh] = 1.f / fmaxf(den[hh], 1e-16f);
    }
    __syncwarp();

    constexpr int NF = F / 32;
    float acc[NF] = {};
    for (int i = 0; i < deg; i++) {
        int s;
        float al[H];
        if (i < CAP) {
            s = shsrc[w][i];
            #pragma unroll
            for (int hh = 0; hh < H; hh++) al[hh] = shex[w][i * H + hh] * inv[hh];
        } else {
            s = col[start + i];
            #pragma unroll
            for (int hh = 0; hh < H; hh++) {
                float v = es[s * H + hh] + edv[hh];
                v = (v > 0.f) ? v : 0.2f * v;
                al[hh] = expf(v - mx[hh]) * inv[hh];
            }
        }
        const float* hr = h + (size_t)s * F;
        #pragma unroll
        for (int fc = 0; fc < NF; fc++) {
            int hh = (fc * 32) / C;
            acc[fc] = fmaf(al[hh], hr[fc * 32 + lane], acc[fc]);
        }
    }
    #pragma unroll
    for (int fc = 0; fc < NF; fc++) {
        int f = fc * 32 + lane;
        float v = acc[fc] + bias[f];
        if (do_elu) v = (v > 0.f) ? v : expm1f(v);
        out[(size_t)d * F + f] = v;
    }
}

// ================= pooling =================
__global__ void pool_feat_kernel(const float* __restrict__ h, const int* __restrict__ batch,
                                 float* __restrict__ pool, int N, int F) {
    int t = blockIdx.x * blockDim.x + threadIdx.x;
    if (t >= N * F) return;
    int n = t / F, f = t % F;
    atomicAdd(&pool[batch[n] * F + f], h[(size_t)n * F + f]);
}
__global__ void pool_cnt_kernel(const int* __restrict__ batch, float* __restrict__ cnt, int N) {
    int t = blockIdx.x * blockDim.x + threadIdx.x;
    if (t < N) atomicAdd(&cnt[batch[t]], 1.0f);
}
__global__ void zero_pool_kernel(float* __restrict__ pool, float* __restrict__ cnt, int G) {
    int t = blockIdx.x * blockDim.x + threadIdx.x;
    if (t < G * 128) pool[t] = 0.f;
    if (t < G) cnt[t] = 0.f;
}

// ================= MLP readout =================
__global__ void mlp_kernel(const float* __restrict__ pool, const float* __restrict__ cnt,
                           const float* __restrict__ mW0, const float* __restrict__ mb0,
                           const float* __restrict__ mW1, const float* __restrict__ mb1,
                           const float* __restrict__ mW2, const float* __restrict__ mb2,
                           float* __restrict__ out, int G) {
    __shared__ float p[128], y1[64], y2[32];
    int g = blockIdx.x, t = threadIdx.x;
    if (g >= G) return;
    float c = fmaxf(cnt[g], 1.0f);
    p[t] = pool[(size_t)g * 128 + t] / c;
    __syncthreads();
    if (t < 64) {
        float s = mb0[t];
        #pragma unroll 8
        for (int i = 0; i < 128; i++) s += p[i] * mW0[i * 64 + t];
        y1[t] = fmaxf(s, 0.0f);
    }
    __syncthreads();
    if (t < 32) {
        float s = mb1[t];
        #pragma unroll 8
        for (int i = 0; i < 64; i++) s += y1[i] * mW1[i * 32 + t];
        y2[t] = fmaxf(s, 0.0f);
    }
    __syncthreads();
    if (t < 4) {
        float s = mb2[t];
        #pragma unroll
        for (int i = 0; i < 32; i++) s += y2[i] * mW2[i * 4 + t];
        out[g * 4 + t] = s;
    }
}

// ================= host orchestration =================
extern "C" void kernel_launch(void* const* d_in, const int* in_sizes, int n_in,
                              void* d_out, int out_size) {
    const float* x     = (const float*)d_in[0];
    const int*   ei    = (const int*)d_in[1];
    const int*   batch = (const int*)d_in[2];
    const float* W0  = (const float*)d_in[4];
    const float* as0 = (const float*)d_in[5];
    const float* ad0 = (const float*)d_in[6];
    const float* b0  = (const float*)d_in[7];
    const float* W1  = (const float*)d_in[8];
    const float* as1 = (const float*)d_in[9];
    const float* ad1 = (const float*)d_in[10];
    const float* b1  = (const float*)d_in[11];
    const float* W2  = (const float*)d_in[12];
    const float* as2 = (const float*)d_in[13];
    const float* ad2 = (const float*)d_in[14];
    const float* b2  = (const float*)d_in[15];
    const float* W3  = (const float*)d_in[16];
    const float* as3 = (const float*)d_in[17];
    const float* ad3 = (const float*)d_in[18];
    const float* b3  = (const float*)d_in[19];
    const float* mW0 = (const float*)d_in[20];
    const float* mb0 = (const float*)d_in[21];
    const float* mW1 = (const float*)d_in[22];
    const float* mb1 = (const float*)d_in[23];
    const float* mW2 = (const float*)d_in[24];
    const float* mb2 = (const float*)d_in[25];

    int N = in_sizes[0] / 64;
    int E = in_sizes[1] / 2;
    int G = out_size / 4;
    int Etot = E + N;

    float *bufA, *bufB, *bufC, *esrc, *edst, *pool, *cnt;
    int *rowptr, *fill, *col, *blksum;
    cudaGetSymbolAddress((void**)&bufA, g_bufA);
    cudaGetSymbolAddress((void**)&bufB, g_bufB);
    cudaGetSymbolAddress((void**)&bufC, g_bufC);
    cudaGetSymbolAddress((void**)&esrc, g_esrc);
    cudaGetSymbolAddress((void**)&edst, g_edst);
    cudaGetSymbolAddress((void**)&pool, g_pool);
    cudaGetSymbolAddress((void**)&cnt,  g_cnt);
    cudaGetSymbolAddress((void**)&rowptr, g_rowptr);
    cudaGetSymbolAddress((void**)&fill,   g_fill);
    cudaGetSymbolAddress((void**)&col,    g_col);
    cudaGetSymbolAddress((void**)&blksum, g_blksum);

    // ---- build CSR ----
    count_init_kernel<<<(N + 255) / 256, 256>>>(fill, N);
    count_edges_kernel<<<(E + 255) / 256, 256>>>(ei, fill, E);
    int nb = (N + 1023) / 1024;
    scan_block_kernel<<<nb, 256>>>(fill, rowptr, blksum, N);
    scan_sums_kernel<<<1, 256>>>(blksum, nb);
    add_off_kernel<<<(N + 255) / 256, 256>>>(rowptr, blksum, N, Etot);
    copy_fill_kernel<<<(N + 255) / 256, 256>>>(rowptr, fill, N);
    fill_kernel<<<(Etot + 255) / 256, 256>>>(ei, fill, col, E, N);

    int gy = (N + 127) / 128;
    // ---- layer 0: x[N,64] -> bufB[N,256] ----
    gemm_tf32_kernel<<<dim3(2, gy), 256>>>(x, W0, bufA, N, 64, 256);
    scores_kernel<<<(N * 4 * 32 + 255) / 256, 256>>>(bufA, as0, ad0, esrc, edst, N, 4, 64);
    gat_gather_kernel<4, 64><<<(N + 7) / 8, 256>>>(bufA, esrc, edst, rowptr, col, b0, bufB, N, 1);
    // ---- layer 1 ----
    gemm_tf32_kernel<<<dim3(2, gy), 256>>>(bufB, W1, bufA, N, 256, 256);
    scores_kernel<<<(N * 4 * 32 + 255) / 256, 256>>>(bufA, as1, ad1, esrc, edst, N, 4, 64);
    gat_gather_kernel<4, 64><<<(N + 7) / 8, 256>>>(bufA, esrc, edst, rowptr, col, b1, bufC, N, 1);
    // ---- layer 2 ----
    gemm_tf32_kernel<<<dim3(2, gy), 256>>>(bufC, W2, bufA, N, 256, 256);
    scores_kernel<<<(N * 4 * 32 + 255) / 256, 256>>>(bufA, as2, ad2, esrc, edst, N, 4, 64);
    gat_gather_kernel<4, 64><<<(N + 7) / 8, 256>>>(bufA, esrc, edst, rowptr, col, b2, bufB, N, 1);
    // ---- layer 3: H=1, C=128, no ELU ----
    gemm_tf32_kernel<<<dim3(1, gy), 256>>>(bufB, W3, bufA, N, 256, 128);
    scores_kernel<<<(N * 1 * 32 + 255) / 256, 256>>>(bufA, as3, ad3, esrc, edst, N, 1, 128);
    gat_gather_kernel<1, 128><<<(N + 7) / 8, 256>>>(bufA, esrc, edst, rowptr, col, b3, bufC, N, 0);

    // ---- global mean pool ----
    zero_pool_kernel<<<(G * 128 + 255) / 256, 256>>>(pool, cnt, G);
    pool_feat_kernel<<<(N * 128 + 255) / 256, 256>>>(bufC, batch, pool, N, 128);
    pool_cnt_kernel<<<(N + 255) / 256, 256>>>(batch, cnt, N);

    // ---- MLP readout ----
    mlp_kernel<<<G, 128>>>(pool, cnt, mW0, mb0, mW1, mb1, mW2, mb2, (float*)d_out, G);
}

// round 4
// speedup vs baseline: 3.9520x; 1.2375x over previous
#include <cuda_runtime.h>
#include <math.h>
#include <float.h>

#define NMAX 100000
#define EMAX 400000
#define ETOTMAX (EMAX + NMAX)
#define GMAX 4096
#define FMAX 256

// ---------------- scratch ----------------
__device__ float g_bufA[NMAX * FMAX];
__device__ float g_bufB[NMAX * FMAX];
__device__ float g_bufC[NMAX * FMAX];
__device__ float g_esrc[NMAX * 4];
__device__ float g_edst[NMAX * 4];
__device__ int g_rowptr[NMAX + 1];
__device__ int g_fill[NMAX];
__device__ int g_col[ETOTMAX];
__device__ int g_blksum[512];
__device__ int g_gstart[GMAX + 1];

// ================= CSR build =================
__global__ void count_init_kernel(int* __restrict__ cnt, int N) {
    int t = blockIdx.x * blockDim.x + threadIdx.x;
    if (t < N) cnt[t] = 1;
}
__global__ void count_edges_kernel(const int* __restrict__ ei, int* __restrict__ cnt, int E) {
    int t = blockIdx.x * blockDim.x + threadIdx.x;
    if (t < E) atomicAdd(&cnt[ei[E + t]], 1);
}
__global__ void scan_block_kernel(const int* __restrict__ in, int* __restrict__ out,
                                  int* __restrict__ blksum, int n) {
    __shared__ int wsum[8];
    int t = threadIdx.x, blk = blockIdx.x;
    int base = blk * 1024 + t * 4;
    int v0 = (base + 0 < n) ? in[base + 0] : 0;
    int v1 = (base + 1 < n) ? in[base + 1] : 0;
    int v2 = (base + 2 < n) ? in[base + 2] : 0;
    int v3 = (base + 3 < n) ? in[base + 3] : 0;
    int tsum = v0 + v1 + v2 + v3;
    int lane = t & 31, w = t >> 5;
    int x = tsum;
    #pragma unroll
    for (int o = 1; o < 32; o <<= 1) {
        int y = __shfl_up_sync(0xffffffffu, x, o);
        if (lane >= o) x += y;
    }
    if (lane == 31) wsum[w] = x;
    __syncthreads();
    if (t < 8) {
        int y = wsum[t];
        #pragma unroll
        for (int o = 1; o < 8; o <<= 1) {
            int z = __shfl_up_sync(0xffu, y, o);
            if (t >= o) y += z;
        }
        wsum[t] = y;
    }
    __syncthreads();
    int woff = (w > 0) ? wsum[w - 1] : 0;
    int excl = woff + x - tsum;
    if (base + 0 < n) out[base + 0] = excl;
    if (base + 1 < n) out[base + 1] = excl + v0;
    if (base + 2 < n) out[base + 2] = excl + v0 + v1;
    if (base + 3 < n) out[base + 3] = excl + v0 + v1 + v2;
    if (t == 255) blksum[blk] = wsum[7];
}
__global__ void scan_sums_kernel(int* __restrict__ blksum, int nb) {
    __shared__ int sh[512];
    int t = threadIdx.x;
    int v = (t < nb) ? blksum[t] : 0;
    sh[t] = v;
    __syncthreads();
    for (int o = 1; o < 256; o <<= 1) {
        int y = (t >= o) ? sh[t - o] : 0;
        __syncthreads();
        sh[t] += y;
        __syncthreads();
    }
    if (t < nb) blksum[t] = sh[t] - v;
}
__global__ void add_off_kernel(int* __restrict__ out, const int* __restrict__ blksum, int n,
                               int tail_val) {
    int t = blockIdx.x * blockDim.x + threadIdx.x;
    if (t < n) out[t] += blksum[t >> 10];
    if (t == 0) out[n] = tail_val;
}
__global__ void copy_fill_kernel(const int* __restrict__ rowptr, int* __restrict__ fill, int N) {
    int t = blockIdx.x * blockDim.x + threadIdx.x;
    if (t < N) fill[t] = rowptr[t];
}
__global__ void fill_kernel(const int* __restrict__ ei, int* __restrict__ fill,
                            int* __restrict__ col, int E, int N) {
    int t = blockIdx.x * blockDim.x + threadIdx.x;
    int Etot = E + N;
    if (t >= Etot) return;
    int s, d;
    if (t < E) { s = ei[t]; d = ei[E + t]; } else { s = d = t - E; }
    int pos = atomicAdd(&fill[d], 1);
    col[pos] = s;
}
// gstart[g] = first node n with batch[n] >= g (batch sorted)
__global__ void gstart_kernel(const int* __restrict__ batch, int* __restrict__ gstart,
                              int N, int G) {
    int n = blockIdx.x * blockDim.x + threadIdx.x;
    if (n > N) return;
    int b = (n < N) ? batch[n] : G;
    int pb = (n > 0) ? batch[n - 1] : -1;
    for (int g = pb + 1; g <= b; g++) gstart[g] = n;
}
__global__ void zero_scores_kernel(float* __restrict__ es, float* __restrict__ ed, int n) {
    int t = blockIdx.x * blockDim.x + threadIdx.x;
    if (t < n) { es[t] = 0.f; ed[t] = 0.f; }
}

// ================= TF32 GEMM + fused score epilogue =================
// C[M,Ncol] = A[M,K] @ B[K,Ncol]. BM=128, BN=128, BK=16, 8 warps (4Mx2N), warp 32x64.
// Each warp's 64-col span lies within one head (C_head=64 -> exactly one head;
// C_head=128 -> head 0 for both warps). Epilogue dots acc rows with a_s/a_d and
// atomicAdds into zero-initialized esrc/edst.
#define AS_STRIDE 20
#define BS_STRIDE 136
__global__ void __launch_bounds__(256, 2)
gemm_tf32_scores_kernel(const float* __restrict__ A, const float* __restrict__ B,
                        float* __restrict__ C, int M, int K, int Ncol,
                        const float* __restrict__ a_s, const float* __restrict__ a_d,
                        float* __restrict__ esrc, float* __restrict__ edst,
                        int H, int Chead) {
    __shared__ unsigned As[128 * AS_STRIDE];
    __shared__ unsigned Bs[16 * BS_STRIDE];

    const int tid = threadIdx.x;
    const int bm = blockIdx.y * 128;
    const int bn = blockIdx.x * 128;
    const int warp = tid >> 5, lane = tid & 31;
    const int g = lane >> 2, tg = lane & 3;
    const int warp_m = (warp & 3) * 32;
    const int warp_n = (warp >> 2) * 64;

    float4 pa[2], pb[2];
    #pragma unroll
    for (int u = 0; u < 2; u++) {
        int ia = tid + u * 256;
        int am = ia >> 2, akq = ia & 3;
        pa[u] = (bm + am < M) ? *(const float4*)(A + (size_t)(bm + am) * K + akq * 4)
                              : make_float4(0.f, 0.f, 0.f, 0.f);
        int ib = tid + u * 256;
        int bk = ib >> 5, bn4 = (ib & 31) * 4;
        pb[u] = *(const float4*)(B + (size_t)bk * Ncol + bn + bn4);
    }

    float acc[2][8][4];
    #pragma unroll
    for (int mt = 0; mt < 2; mt++)
        #pragma unroll
        for (int nt = 0; nt < 8; nt++)
            #pragma unroll
            for (int r = 0; r < 4; r++) acc[mt][nt][r] = 0.f;

    for (int k0 = 0; k0 < K; k0 += 16) {
        #pragma unroll
        for (int u = 0; u < 2; u++) {
            int ia = tid + u * 256;
            int am = ia >> 2, akq = (ia & 3) * 4;
            unsigned t0, t1, t2, t3;
            asm("cvt.rna.tf32.f32 %0, %1;" : "=r"(t0) : "f"(pa[u].x));
            asm("cvt.rna.tf32.f32 %0, %1;" : "=r"(t1) : "f"(pa[u].y));
            asm("cvt.rna.tf32.f32 %0, %1;" : "=r"(t2) : "f"(pa[u].z));
            asm("cvt.rna.tf32.f32 %0, %1;" : "=r"(t3) : "f"(pa[u].w));
            As[am * AS_STRIDE + akq + 0] = t0;
            As[am * AS_STRIDE + akq + 1] = t1;
            As[am * AS_STRIDE + akq + 2] = t2;
            As[am * AS_STRIDE + akq + 3] = t3;
            int ib = tid + u * 256;
            int bk = ib >> 5, bn4 = (ib & 31) * 4;
            asm("cvt.rna.tf32.f32 %0, %1;" : "=r"(t0) : "f"(pb[u].x));
            asm("cvt.rna.tf32.f32 %0, %1;" : "=r"(t1) : "f"(pb[u].y));
            asm("cvt.rna.tf32.f32 %0, %1;" : "=r"(t2) : "f"(pb[u].z));
            asm("cvt.rna.tf32.f32 %0, %1;" : "=r"(t3) : "f"(pb[u].w));
            Bs[bk * BS_STRIDE + bn4 + 0] = t0;
            Bs[bk * BS_STRIDE + bn4 + 1] = t1;
            Bs[bk * BS_STRIDE + bn4 + 2] = t2;
            Bs[bk * BS_STRIDE + bn4 + 3] = t3;
        }
        __syncthreads();

        if (k0 + 16 < K) {
            #pragma unroll
            for (int u = 0; u < 2; u++) {
                int ia = tid + u * 256;
                int am = ia >> 2, akq = ia & 3;
                pa[u] = (bm + am < M)
                    ? *(const float4*)(A + (size_t)(bm + am) * K + k0 + 16 + akq * 4)
                    : make_float4(0.f, 0.f, 0.f, 0.f);
                int ib = tid + u * 256;
                int bk = ib >> 5, bn4 = (ib & 31) * 4;
                pb[u] = *(const float4*)(B + (size_t)(k0 + 16 + bk) * Ncol + bn + bn4);
            }
        }

        #pragma unroll
        for (int kk = 0; kk < 2; kk++) {
            unsigned afr[2][4], bfr[8][2];
            #pragma unroll
            for (int mt = 0; mt < 2; mt++) {
                int r0 = warp_m + mt * 16 + g;
                afr[mt][0] = As[r0 * AS_STRIDE + kk * 8 + tg];
                afr[mt][1] = As[(r0 + 8) * AS_STRIDE + kk * 8 + tg];
                afr[mt][2] = As[r0 * AS_STRIDE + kk * 8 + tg + 4];
                afr[mt][3] = As[(r0 + 8) * AS_STRIDE + kk * 8 + tg + 4];
            }
            #pragma unroll
            for (int nt = 0; nt < 8; nt++) {
                int c = warp_n + nt * 8 + g;
                bfr[nt][0] = Bs[(kk * 8 + tg) * BS_STRIDE + c];
                bfr[nt][1] = Bs[(kk * 8 + tg + 4) * BS_STRIDE + c];
            }
            #pragma unroll
            for (int mt = 0; mt < 2; mt++)
                #pragma unroll
                for (int nt = 0; nt < 8; nt++) {
                    asm volatile(
                        "mma.sync.aligned.m16n8k8.row.col.f32.tf32.tf32.f32 "
                        "{%0,%1,%2,%3}, {%4,%5,%6,%7}, {%8,%9}, {%0,%1,%2,%3};"
                        : "+f"(acc[mt][nt][0]), "+f"(acc[mt][nt][1]),
                          "+f"(acc[mt][nt][2]), "+f"(acc[mt][nt][3])
                        : "r"(afr[mt][0]), "r"(afr[mt][1]), "r"(afr[mt][2]), "r"(afr[mt][3]),
                          "r"(bfr[nt][0]), "r"(bfr[nt][1]));
                }
        }
        __syncthreads();
    }

    // ---- epilogue: store C + fused scores ----
    const int hh = (bn + warp_n) / Chead;
    #pragma unroll
    for (int mt = 0; mt < 2; mt++) {
        int r0 = bm + warp_m + mt * 16 + g;
        int r1 = r0 + 8;
        float ps0 = 0.f, pd0 = 0.f, ps1 = 0.f, pd1 = 0.f;
        #pragma unroll
        for (int nt = 0; nt < 8; nt++) {
            int c = bn + warp_n + nt * 8 + 2 * tg;
            float asv0 = a_s[c], asv1 = a_s[c + 1];
            float adv0 = a_d[c], adv1 = a_d[c + 1];
            ps0 += acc[mt][nt][0] * asv0 + acc[mt][nt][1] * asv1;
            pd0 += acc[mt][nt][0] * adv0 + acc[mt][nt][1] * adv1;
            ps1 += acc[mt][nt][2] * asv0 + acc[mt][nt][3] * asv1;
            pd1 += acc[mt][nt][2] * adv0 + acc[mt][nt][3] * adv1;
            int cc = c - bm; (void)cc;
            if (r0 < M) *(float2*)(C + (size_t)r0 * Ncol + c) = make_float2(acc[mt][nt][0], acc[mt][nt][1]);
            if (r1 < M) *(float2*)(C + (size_t)r1 * Ncol + c) = make_float2(acc[mt][nt][2], acc[mt][nt][3]);
        }
        // reduce over the 4 tg lanes (low 2 bits of lane)
        #pragma unroll
        for (int o = 1; o < 4; o <<= 1) {
            ps0 += __shfl_xor_sync(0xffffffffu, ps0, o);
            pd0 += __shfl_xor_sync(0xffffffffu, pd0, o);
            ps1 += __shfl_xor_sync(0xffffffffu, ps1, o);
            pd1 += __shfl_xor_sync(0xffffffffu, pd1, o);
        }
        if (tg == 0) {
            if (r0 < M) {
                atomicAdd(&esrc[r0 * H + hh], ps0);
                atomicAdd(&edst[r0 * H + hh], pd0);
            }
            if (r1 < M) {
                atomicAdd(&esrc[r1 * H + hh], ps1);
                atomicAdd(&edst[r1 * H + hh], pd1);
            }
        }
    }
}

// ================= fused gather: softmax + aggregate + bias + ELU =================
template<int H, int C>
__global__ void gat_gather_kernel(const float* __restrict__ h,
                                  const float* __restrict__ es, const float* __restrict__ ed,
                                  const int* __restrict__ rowptr, const int* __restrict__ col,
                                  const float* __restrict__ bias, float* __restrict__ out,
                                  int N, int do_elu) {
    constexpr int F = H * C;
    constexpr int CAP = 64;
    constexpr int NW = 8;
    __shared__ float shex[NW][CAP * H];
    __shared__ int   shsrc[NW][CAP];
    const int w = threadIdx.x >> 5, lane = threadIdx.x & 31;
    const int d = blockIdx.x * NW + w;
    if (d >= N) return;
    const int start = rowptr[d];
    const int deg = rowptr[d + 1] - start;

    float edv[H], mx[H];
    #pragma unroll
    for (int hh = 0; hh < H; hh++) { edv[hh] = ed[d * H + hh]; mx[hh] = -FLT_MAX; }

    for (int i0 = 0; i0 < deg; i0 += 32) {
        int i = i0 + lane;
        if (i < deg) {
            int s = col[start + i];
            if (i < CAP) shsrc[w][i] = s;
            #pragma unroll
            for (int hh = 0; hh < H; hh++) {
                float v = es[s * H + hh] + edv[hh];
                v = (v > 0.f) ? v : 0.2f * v;
                if (i < CAP) shex[w][i * H + hh] = v;
                mx[hh] = fmaxf(mx[hh], v);
            }
        }
    }
    #pragma unroll
    for (int hh = 0; hh < H; hh++)
        #pragma unroll
        for (int o = 16; o; o >>= 1) mx[hh] = fmaxf(mx[hh], __shfl_xor_sync(0xffffffffu, mx[hh], o));
    __syncwarp();

    float den[H];
    #pragma unroll
    for (int hh = 0; hh < H; hh++) den[hh] = 0.f;
    for (int i0 = 0; i0 < deg; i0 += 32) {
        int i = i0 + lane;
        if (i < deg) {
            int s = (i < CAP) ? shsrc[w][i] : col[start + i];
            #pragma unroll
            for (int hh = 0; hh < H; hh++) {
                float v;
                if (i < CAP) v = shex[w][i * H + hh];
                else { v = es[s * H + hh] + edv[hh]; v = (v > 0.f) ? v : 0.2f * v; }
                float ex = expf(v - mx[hh]);
                if (i < CAP) shex[w][i * H + hh] = ex;
                den[hh] += ex;
            }
        }
    }
    float inv[H];
    #pragma unroll
    for (int hh = 0; hh < H; hh++) {
        #pragma unroll
        for (int o = 16; o; o >>= 1) den[hh] += __shfl_xor_sync(0xffffffffu, den[hh], o);
        inv[hh] = 1.f / fmaxf(den[hh], 1e-16f);
    }
    __syncwarp();

    constexpr int NF = F / 32;
    float acc[NF] = {};
    for (int i = 0; i < deg; i++) {
        int s;
        float al[H];
        if (i < CAP) {
            s = shsrc[w][i];
            #pragma unroll
            for (int hh = 0; hh < H; hh++) al[hh] = shex[w][i * H + hh] * inv[hh];
        } else {
            s = col[start + i];
            #pragma unroll
            for (int hh = 0; hh < H; hh++) {
                float v = es[s * H + hh] + edv[hh];
                v = (v > 0.f) ? v : 0.2f * v;
                al[hh] = expf(v - mx[hh]) * inv[hh];
            }
        }
        const float* hr = h + (size_t)s * F;
        #pragma unroll
        for (int fc = 0; fc < NF; fc++) {
            int hh = (fc * 32) / C;
            acc[fc] = fmaf(al[hh], hr[fc * 32 + lane], acc[fc]);
        }
    }
    #pragma unroll
    for (int fc = 0; fc < NF; fc++) {
        int f = fc * 32 + lane;
        float v = acc[fc] + bias[f];
        if (do_elu) v = (v > 0.f) ? v : expm1f(v);
        out[(size_t)d * F + f] = v;
    }
}

// ================= fused pool + MLP readout =================
__global__ void pool_mlp_kernel(const float* __restrict__ h, const int* __restrict__ gstart,
                                const float* __restrict__ mW0, const float* __restrict__ mb0,
                                const float* __restrict__ mW1, const float* __restrict__ mb1,
                                const float* __restrict__ mW2, const float* __restrict__ mb2,
                                float* __restrict__ out, int G) {
    __shared__ float p[128], y1[64], y2[32];
    int g = blockIdx.x, t = threadIdx.x;
    if (g >= G) return;
    int s = gstart[g], e = gstart[g + 1];
    float acc = 0.f;
    for (int n = s; n < e; n++) acc += h[(size_t)n * 128 + t];
    float c = fmaxf((float)(e - s), 1.0f);
    p[t] = acc / c;
    __syncthreads();
    if (t < 64) {
        float sum = mb0[t];
        #pragma unroll 8
        for (int i = 0; i < 128; i++) sum += p[i] * mW0[i * 64 + t];
        y1[t] = fmaxf(sum, 0.0f);
    }
    __syncthreads();
    if (t < 32) {
        float sum = mb1[t];
        #pragma unroll 8
        for (int i = 0; i < 64; i++) sum += y1[i] * mW1[i * 32 + t];
        y2[t] = fmaxf(sum, 0.0f);
    }
    __syncthreads();
    if (t < 4) {
        float sum = mb2[t];
        #pragma unroll
        for (int i = 0; i < 32; i++) sum += y2[i] * mW2[i * 4 + t];
        out[g * 4 + t] = sum;
    }
}

// ================= host orchestration =================
extern "C" void kernel_launch(void* const* d_in, const int* in_sizes, int n_in,
                              void* d_out, int out_size) {
    const float* x     = (const float*)d_in[0];
    const int*   ei    = (const int*)d_in[1];
    const int*   batch = (const int*)d_in[2];
    const float* W0  = (const float*)d_in[4];
    const float* as0 = (const float*)d_in[5];
    const float* ad0 = (const float*)d_in[6];
    const float* b0  = (const float*)d_in[7];
    const float* W1  = (const float*)d_in[8];
    const float* as1 = (const float*)d_in[9];
    const float* ad1 = (const float*)d_in[10];
    const float* b1  = (const float*)d_in[11];
    const float* W2  = (const float*)d_in[12];
    const float* as2 = (const float*)d_in[13];
    const float* ad2 = (const float*)d_in[14];
    const float* b2  = (const float*)d_in[15];
    const float* W3  = (const float*)d_in[16];
    const float* as3 = (const float*)d_in[17];
    const float* ad3 = (const float*)d_in[18];
    const float* b3  = (const float*)d_in[19];
    const float* mW0 = (const float*)d_in[20];
    const float* mb0 = (const float*)d_in[21];
    const float* mW1 = (const float*)d_in[22];
    const float* mb1 = (const float*)d_in[23];
    const float* mW2 = (const float*)d_in[24];
    const float* mb2 = (const float*)d_in[25];

    int N = in_sizes[0] / 64;
    int E = in_sizes[1] / 2;
    int G = out_size / 4;
    int Etot = E + N;

    float *bufA, *bufB, *bufC, *esrc, *edst;
    int *rowptr, *fill, *col, *blksum, *gstart;
    cudaGetSymbolAddress((void**)&bufA, g_bufA);
    cudaGetSymbolAddress((void**)&bufB, g_bufB);
    cudaGetSymbolAddress((void**)&bufC, g_bufC);
    cudaGetSymbolAddress((void**)&esrc, g_esrc);
    cudaGetSymbolAddress((void**)&edst, g_edst);
    cudaGetSymbolAddress((void**)&rowptr, g_rowptr);
    cudaGetSymbolAddress((void**)&fill,   g_fill);
    cudaGetSymbolAddress((void**)&col,    g_col);
    cudaGetSymbolAddress((void**)&blksum, g_blksum);
    cudaGetSymbolAddress((void**)&gstart, g_gstart);

    // ---- build CSR + graph segments ----
    count_init_kernel<<<(N + 255) / 256, 256>>>(fill, N);
    count_edges_kernel<<<(E + 255) / 256, 256>>>(ei, fill, E);
    int nb = (N + 1023) / 1024;
    scan_block_kernel<<<nb, 256>>>(fill, rowptr, blksum, N);
    scan_sums_kernel<<<1, 256>>>(blksum, nb);
    add_off_kernel<<<(N + 255) / 256, 256>>>(rowptr, blksum, N, Etot);
    copy_fill_kernel<<<(N + 255) / 256, 256>>>(rowptr, fill, N);
    fill_kernel<<<(Etot + 255) / 256, 256>>>(ei, fill, col, E, N);
    gstart_kernel<<<(N + 256) / 256, 256>>>(batch, gstart, N, G);

    int gy = (N + 127) / 128;
    // ---- layer 0: x[N,64] -> bufB[N,256] ----
    zero_scores_kernel<<<(N * 4 + 255) / 256, 256>>>(esrc, edst, N * 4);
    gemm_tf32_scores_kernel<<<dim3(2, gy), 256>>>(x, W0, bufA, N, 64, 256, as0, ad0, esrc, edst, 4, 64);
    gat_gather_kernel<4, 64><<<(N + 7) / 8, 256>>>(bufA, esrc, edst, rowptr, col, b0, bufB, N, 1);
    // ---- layer 1 ----
    zero_scores_kernel<<<(N * 4 + 255) / 256, 256>>>(esrc, edst, N * 4);
    gemm_tf32_scores_kernel<<<dim3(2, gy), 256>>>(bufB, W1, bufA, N, 256, 256, as1, ad1, esrc, edst, 4, 64);
    gat_gather_kernel<4, 64><<<(N + 7) / 8, 256>>>(bufA, esrc, edst, rowptr, col, b1, bufC, N, 1);
    // ---- layer 2 ----
    zero_scores_kernel<<<(N * 4 + 255) / 256, 256>>>(esrc, edst, N * 4);
    gemm_tf32_scores_kernel<<<dim3(2, gy), 256>>>(bufC, W2, bufA, N, 256, 256, as2, ad2, esrc, edst, 4, 64);
    gat_gather_kernel<4, 64><<<(N + 7) / 8, 256>>>(bufA, esrc, edst, rowptr, col, b2, bufB, N, 1);
    // ---- layer 3: H=1, C=128, no ELU ----
    zero_scores_kernel<<<(N + 255) / 256, 256>>>(esrc, edst, N);
    gemm_tf32_scores_kernel<<<dim3(1, gy), 256>>>(bufB, W3, bufA, N, 256, 128, as3, ad3, esrc, edst, 1, 128);
    gat_gather_kernel<1, 128><<<(N + 7) / 8, 256>>>(bufA, esrc, edst, rowptr, col, b3, bufC, N, 0);

    // ---- fused pool + MLP ----
    pool_mlp_kernel<<<G, 128>>>(bufC, gstart, mW0, mb0, mW1, mb1, mW2, mb2, (float*)d_out, G);
}